// round 5
// baseline (speedup 1.0000x reference)
#include <cuda_runtime.h>
#include <cstdint>
#include <math.h>

#define NB   8192
#define FST  257

__device__ unsigned g_m1[NB * 8];
__device__ unsigned g_m2[NB * 8];
__device__ float    g_f[NB * 64];
__device__ float    g_G[256 * 256];   // W1 @ W1^T
__device__ float    g_W3T[256 * 64];  // W3 transposed: [i][o]

typedef unsigned long long ull;
static __device__ __forceinline__ ull dup2(float x) {
    unsigned xi = __float_as_uint(x); ull r;
    asm("mov.b64 %0, {%1, %1};" : "=l"(r) : "r"(xi)); return r;
}
static __device__ __forceinline__ ull fma2(ull a, ull b, ull c) {
    ull d; asm("fma.rn.f32x2 %0, %1, %2, %3;" : "=l"(d) : "l"(a), "l"(b), "l"(c)); return d;
}
static __device__ __forceinline__ float2 unp2(ull v) {
    unsigned lo, hi; asm("mov.b64 {%0, %1}, %2;" : "=r"(lo), "=r"(hi) : "l"(v));
    return make_float2(__uint_as_float(lo), __uint_as_float(hi));
}

// ============ fwd (blocks 0..127) + gram/W3T (blocks 128..143) ============
__global__ void __launch_bounds__(256, 1)
fwdgram_kernel(const float* __restrict__ x,
               const float* __restrict__ W1, const float* __restrict__ b1,
               const float* __restrict__ W2, const float* __restrict__ b2,
               const float* __restrict__ W3, const float* __restrict__ b3)
{
    extern __shared__ float sm[];
    const int tid = threadIdx.x;
    const int tx = tid & 15, ty = tid >> 4;

    if (blockIdx.x >= 128) {
        // ---- gram branch: G = W1 W1^T (16 tiles of 64x64) + W3T fill ----
        float* At  = sm;             // [64][65]
        float* Bt2 = sm + 64 * 65;   // [64][65]
        const int t = blockIdx.x - 128;
        const int bi = t >> 2, bj = t & 3;

        for (int e = t * 256 + tid; e < 256 * 64; e += 16 * 256) {
            int i = e >> 6, o = e & 63;
            g_W3T[e] = W3[(size_t)o * 256 + i];
        }

        float acc[4][4];
        #pragma unroll
        for (int i = 0; i < 4; i++)
            #pragma unroll
            for (int u = 0; u < 4; u++) acc[i][u] = 0.f;

        for (int kc = 0; kc < 4; kc++) {
            __syncthreads();
            for (int e = tid; e < 64 * 16; e += 256) {
                int r = e >> 4, c4 = e & 15;
                float4 va = reinterpret_cast<const float4*>(W1)[(size_t)(bi * 64 + r) * 64 + kc * 16 + c4];
                At[r * 65 + c4 * 4 + 0] = va.x; At[r * 65 + c4 * 4 + 1] = va.y;
                At[r * 65 + c4 * 4 + 2] = va.z; At[r * 65 + c4 * 4 + 3] = va.w;
                float4 vb = reinterpret_cast<const float4*>(W1)[(size_t)(bj * 64 + r) * 64 + kc * 16 + c4];
                Bt2[r * 65 + c4 * 4 + 0] = vb.x; Bt2[r * 65 + c4 * 4 + 1] = vb.y;
                Bt2[r * 65 + c4 * 4 + 2] = vb.z; Bt2[r * 65 + c4 * 4 + 3] = vb.w;
            }
            __syncthreads();
            #pragma unroll 4
            for (int k = 0; k < 64; k++) {
                float a[4], b[4];
                #pragma unroll
                for (int i = 0; i < 4; i++) a[i] = At[(ty * 4 + i) * 65 + k];
                #pragma unroll
                for (int u = 0; u < 4; u++) b[u] = Bt2[(tx * 4 + u) * 65 + k];
                #pragma unroll
                for (int i = 0; i < 4; i++)
                    #pragma unroll
                    for (int u = 0; u < 4; u++)
                        acc[i][u] = fmaf(a[i], b[u], acc[i][u]);
            }
        }
        #pragma unroll
        for (int i = 0; i < 4; i++)
            #pragma unroll
            for (int u = 0; u < 4; u++)
                g_G[(size_t)(bi * 64 + ty * 4 + i) * 256 + bj * 64 + tx * 4 + u] = acc[i][u];
        return;
    }

    // ---- fwd branch (identical math to verified R4 kernel) ----
    float* bufA = sm;
    float* bufB = bufA + 64 * FST;
    float* wt   = bufB + 64 * FST;
    const int s0 = blockIdx.x * 64;

    for (int e = tid; e < 64 * 64; e += 256) {
        int r = e >> 6, c = e & 63;
        float4 v = reinterpret_cast<const float4*>(x)[(size_t)(s0 + r) * 64 + c];
        float* d = &bufA[r * FST + c * 4];
        d[0] = v.x; d[1] = v.y; d[2] = v.z; d[3] = v.w;
    }
    __syncthreads();

    const float* Ws[3] = {W1, W2, W3};
    const float* bs[3] = {b1, b2, b3};
    float* ib = bufA;
    float* ob = bufB;

    for (int L = 0; L < 3; L++) {
        const int HO = (L == 2) ? 64 : 256;
        for (int oc = 0; oc < HO / 64; oc++) {
            __syncthreads();
            for (int e = tid; e < 64 * 64; e += 256) {
                int r = e >> 6, c = e & 63;
                float4 v = reinterpret_cast<const float4*>(Ws[L])[(size_t)(oc * 64 + r) * 64 + c];
                float* d = &wt[r * FST + c * 4];
                d[0] = v.x; d[1] = v.y; d[2] = v.z; d[3] = v.w;
            }
            __syncthreads();

            float acc[4][4];
            #pragma unroll
            for (int u = 0; u < 4; u++) {
                float bv = bs[L][oc * 64 + tx + 16 * u];
                #pragma unroll
                for (int i = 0; i < 4; i++) acc[i][u] = bv;
            }
            #pragma unroll 4
            for (int k = 0; k < 256; k++) {
                float a[4], bv[4];
                #pragma unroll
                for (int i = 0; i < 4; i++) a[i] = ib[(ty * 4 + i) * FST + k];
                #pragma unroll
                for (int u = 0; u < 4; u++) bv[u] = wt[(tx + 16 * u) * FST + k];
                #pragma unroll
                for (int i = 0; i < 4; i++)
                    #pragma unroll
                    for (int u = 0; u < 4; u++)
                        acc[i][u] = fmaf(a[i], bv[u], acc[i][u]);
            }
            if (L < 2) {
                #pragma unroll
                for (int i = 0; i < 4; i++)
                    #pragma unroll
                    for (int u = 0; u < 4; u++)
                        ob[(ty * 4 + i) * FST + oc * 64 + tx + 16 * u] = fmaxf(acc[i][u], 0.f);
            } else {
                #pragma unroll
                for (int i = 0; i < 4; i++)
                    #pragma unroll
                    for (int u = 0; u < 4; u++)
                        g_f[(size_t)(s0 + ty * 4 + i) * 64 + tx + 16 * u] = acc[i][u];
            }
        }
        if (L < 2) {
            __syncthreads();
            unsigned* mg = L ? g_m2 : g_m1;
            for (int e = tid; e < 64 * 8; e += 256) {
                int s = e >> 3, w = e & 7;
                unsigned bits = 0;
                for (int bb = 0; bb < 32; bb++)
                    if (ob[s * FST + w * 32 + bb] > 0.f) bits |= 1u << bb;
                mg[(size_t)(s0 + s) * 8 + w] = bits;
            }
            float* t = ib; ib = ob; ob = t;
            __syncthreads();
        }
    }
}

// ===================== jac kernel v3 =====================
// phase1: Bt[o,j] = sum_{i in S2} W3T[i,o] * W2[i, idx1[j]]   (64 x W window)
// phase2: q = sum_{j,j'} (Bt^T Bt)[j,j'] * G[idx1[j], idx1[j']]
#define CH     16
#define BT_ST  200
#define WG_ST  200
#define AS_ST  68
#define O_BT   0
#define O_WG   12800
#define O_AS   16000
#define O_IDX1 17088
#define O_IDX2 17344
#define O_CNT  17600
#define O_PC   17602
#define O_RED  17618
#define SMEMF  17632
#define SMEMB  (SMEMF * 4)

__global__ void __launch_bounds__(256, 3)
jac_kernel(const float* __restrict__ W2, const float* __restrict__ kp,
           float* __restrict__ out)
{
    extern __shared__ float sm[];
    float* Bt  = sm + O_BT;
    float* Wg  = sm + O_WG;
    float* As  = sm + O_AS;
    int* idx1  = (int*)(sm + O_IDX1);
    int* idx2  = (int*)(sm + O_IDX2);
    int* cnts  = (int*)(sm + O_CNT);
    int* pcnt  = (int*)(sm + O_PC);
    float* red = sm + O_RED;

    const int b = blockIdx.x;
    const int tid = threadIdx.x;

    // ---- mask compaction ----
    idx1[tid] = 0; idx2[tid] = 0;
    if (tid < 16) {
        int which = tid >> 3, w = tid & 7;
        unsigned word = (which ? g_m2 : g_m1)[(size_t)b * 8 + w];
        pcnt[tid] = __popc(word);
    }
    __syncthreads();
    if (tid < 16) {
        int which = tid >> 3, w = tid & 7;
        unsigned word = (which ? g_m2 : g_m1)[(size_t)b * 8 + w];
        int base = 0;
        for (int t = which * 8; t < which * 8 + w; t++) base += pcnt[t];
        int* idx = which ? idx2 : idx1;
        while (word) {
            int bp = __ffs(word) - 1; word &= word - 1;
            idx[base++] = w * 32 + bp;
        }
        if (w == 7) cnts[which] = base;
    }
    __syncthreads();
    const int cnt1 = min(cnts[0], 192);
    const int cnt2 = cnts[1];
    int NP = (cnt1 + 15) & ~15;           // phase2 extent (16-aligned)
    if (NP == 0) NP = 16;
    const int W = (NP <= 128) ? 128 : 192; // phase1 column window
    const int nch = (cnt2 + CH - 1) / CH;

    // ---- phase1 ----
    const int og = tid >> 4;   // 16 groups x 4 o
    const int jg = tid & 15;   // 16 groups x (8 or 12) j
    ull acc[4][6];
    #pragma unroll
    for (int k = 0; k < 4; k++)
        #pragma unroll
        for (int c = 0; c < 6; c++) acc[k][c] = 0ull;

    for (int ch = 0; ch < nch; ch++) {
        const int i0 = ch * CH;
        __syncthreads();
        for (int e = tid; e < CH * 64; e += 256) {
            int ii = e >> 6, o = e & 63;
            As[ii * AS_ST + o] = (i0 + ii < cnt2) ? g_W3T[(size_t)idx2[i0 + ii] * 64 + o] : 0.f;
        }
        for (int e = tid; e < CH * W; e += 256) {
            int ii = e / W, j = e - ii * W;
            Wg[ii * WG_ST + j] = (j < cnt1 && i0 + ii < cnt2)
                ? W2[(size_t)idx2[i0 + ii] * 256 + idx1[j]] : 0.f;
        }
        __syncthreads();
        if (W == 128) {
            #pragma unroll 2
            for (int ii = 0; ii < CH; ii++) {
                const float* as = &As[ii * AS_ST + og * 4];
                const float* wg = &Wg[ii * WG_ST + jg * 8];
                float2 a01 = unp2(*(const ull*)as);
                float2 a23 = unp2(*(const ull*)(as + 2));
                ull w0 = *(const ull*)wg,      w1 = *(const ull*)(wg + 2);
                ull w2v = *(const ull*)(wg + 4), w3v = *(const ull*)(wg + 6);
                ull d0 = dup2(a01.x), d1 = dup2(a01.y), d2 = dup2(a23.x), d3 = dup2(a23.y);
                acc[0][0]=fma2(d0,w0,acc[0][0]); acc[0][1]=fma2(d0,w1,acc[0][1]);
                acc[0][2]=fma2(d0,w2v,acc[0][2]); acc[0][3]=fma2(d0,w3v,acc[0][3]);
                acc[1][0]=fma2(d1,w0,acc[1][0]); acc[1][1]=fma2(d1,w1,acc[1][1]);
                acc[1][2]=fma2(d1,w2v,acc[1][2]); acc[1][3]=fma2(d1,w3v,acc[1][3]);
                acc[2][0]=fma2(d2,w0,acc[2][0]); acc[2][1]=fma2(d2,w1,acc[2][1]);
                acc[2][2]=fma2(d2,w2v,acc[2][2]); acc[2][3]=fma2(d2,w3v,acc[2][3]);
                acc[3][0]=fma2(d3,w0,acc[3][0]); acc[3][1]=fma2(d3,w1,acc[3][1]);
                acc[3][2]=fma2(d3,w2v,acc[3][2]); acc[3][3]=fma2(d3,w3v,acc[3][3]);
            }
        } else {
            #pragma unroll 2
            for (int ii = 0; ii < CH; ii++) {
                const float* as = &As[ii * AS_ST + og * 4];
                const float* wg = &Wg[ii * WG_ST + jg * 12];
                float2 a01 = unp2(*(const ull*)as);
                float2 a23 = unp2(*(const ull*)(as + 2));
                ull wv[6];
                #pragma unroll
                for (int c = 0; c < 6; c++) wv[c] = *(const ull*)(wg + 2 * c);
                ull d0 = dup2(a01.x), d1 = dup2(a01.y), d2 = dup2(a23.x), d3 = dup2(a23.y);
                #pragma unroll
                for (int c = 0; c < 6; c++) {
                    acc[0][c] = fma2(d0, wv[c], acc[0][c]);
                    acc[1][c] = fma2(d1, wv[c], acc[1][c]);
                    acc[2][c] = fma2(d2, wv[c], acc[2][c]);
                    acc[3][c] = fma2(d3, wv[c], acc[3][c]);
                }
            }
        }
    }
    __syncthreads();
    if (W == 128) {
        #pragma unroll
        for (int k = 0; k < 4; k++)
            #pragma unroll
            for (int c = 0; c < 4; c++)
                *(ull*)&Bt[(og * 4 + k) * BT_ST + jg * 8 + 2 * c] = acc[k][c];
    } else {
        #pragma unroll
        for (int k = 0; k < 4; k++)
            #pragma unroll
            for (int c = 0; c < 6; c++)
                *(ull*)&Bt[(og * 4 + k) * BT_ST + jg * 12 + 2 * c] = acc[k][c];
    }
    __syncthreads();

    // ---- phase2: M-tiles 8x4, warp-uniform rows ----
    const int wrp = tid >> 5, lane = tid & 31;
    const int nrg = NP >> 3;   // tiles of 8 rows
    const int ncg = NP >> 2;   // tiles of 4 cols
    float qacc = 0.f;

    for (int rg = wrp; rg < nrg; rg += 8) {
        const int r0 = rg * 8;
        for (int cg = lane; cg < ncg; cg += 32) {
            const int c0 = cg * 4;
            ull m[8][2];
            #pragma unroll
            for (int k = 0; k < 8; k++) { m[k][0] = 0ull; m[k][1] = 0ull; }
            #pragma unroll 2
            for (int o = 0; o < 64; o++) {
                const float* br = &Bt[o * BT_ST];
                ull b0 = *(const ull*)(br + c0), b1 = *(const ull*)(br + c0 + 2);
                #pragma unroll
                for (int kh = 0; kh < 2; kh++) {
                    float2 pa = unp2(*(const ull*)(br + r0 + kh * 4));
                    float2 pb = unp2(*(const ull*)(br + r0 + kh * 4 + 2));
                    ull da = dup2(pa.x), db = dup2(pa.y), dc = dup2(pb.x), dd = dup2(pb.y);
                    m[kh*4+0][0]=fma2(da,b0,m[kh*4+0][0]); m[kh*4+0][1]=fma2(da,b1,m[kh*4+0][1]);
                    m[kh*4+1][0]=fma2(db,b0,m[kh*4+1][0]); m[kh*4+1][1]=fma2(db,b1,m[kh*4+1][1]);
                    m[kh*4+2][0]=fma2(dc,b0,m[kh*4+2][0]); m[kh*4+2][1]=fma2(dc,b1,m[kh*4+2][1]);
                    m[kh*4+3][0]=fma2(dd,b0,m[kh*4+3][0]); m[kh*4+3][1]=fma2(dd,b1,m[kh*4+3][1]);
                }
            }
            const int gc0 = idx1[c0], gc1 = idx1[c0 + 1];
            const int gc2 = idx1[c0 + 2], gc3 = idx1[c0 + 3];
            #pragma unroll
            for (int k = 0; k < 8; k++) {
                const float* Gr = &g_G[(size_t)idx1[r0 + k] * 256];
                float2 m0 = unp2(m[k][0]), m1 = unp2(m[k][1]);
                qacc += m0.x * Gr[gc0] + m0.y * Gr[gc1] + m1.x * Gr[gc2] + m1.y * Gr[gc3];
            }
        }
    }

    // ---- reduce + epilogue ----
    #pragma unroll
    for (int s = 16; s; s >>= 1) qacc += __shfl_xor_sync(0xFFFFFFFFu, qacc, s);
    if ((tid & 31) == 0) red[tid >> 5] = qacc;
    __syncthreads();
    if (tid == 0) {
        float t = 0.f;
        for (int i = 0; i < 8; i++) t += red[i];
        red[0] = t;
    }
    __syncthreads();
    const float qq = red[0];
    if (tid < 64) {
        float fv = g_f[(size_t)b * 64 + tid];
        float kk = kp[0];
        float sp = (kk > 20.f) ? kk : log1pf(expf(kk));
        out[(size_t)b * 64 + tid] = tanhf(sp * fv / (sqrtf(qq) + 1e-4f));
    }
}

extern "C" void kernel_launch(void* const* d_in, const int* in_sizes, int n_in,
                              void* d_out, int out_size) {
    const float* x  = (const float*)d_in[0];
    const float* W1 = (const float*)d_in[1];
    const float* b1 = (const float*)d_in[2];
    const float* W2 = (const float*)d_in[3];
    const float* b2 = (const float*)d_in[4];
    const float* W3 = (const float*)d_in[5];
    const float* b3 = (const float*)d_in[6];
    const float* k  = (const float*)d_in[7];
    float* out = (float*)d_out;

    const size_t sm_fwd = 3 * 64 * FST * sizeof(float);
    cudaFuncSetAttribute(fwdgram_kernel, cudaFuncAttributeMaxDynamicSharedMemorySize, (int)sm_fwd);
    cudaFuncSetAttribute(jac_kernel, cudaFuncAttributeMaxDynamicSharedMemorySize, SMEMB);

    fwdgram_kernel<<<144, 256, sm_fwd>>>(x, W1, b1, W2, b2, W3, b3);
    jac_kernel<<<NB, 256, SMEMB>>>(W2, k, out);
}

// round 6
// speedup vs baseline: 1.3173x; 1.3173x over previous
#include <cuda_runtime.h>
#include <cstdint>
#include <math.h>

#define NB   8192
#define FST  257

__device__ unsigned g_m1[NB * 8];
__device__ unsigned g_m2[NB * 8];
__device__ float    g_f[NB * 64];
__device__ float    g_G[256 * 256];   // W1 @ W1^T (symmetric)
__device__ float    g_W3T[256 * 64];  // W3 transposed: [i][o]

typedef unsigned long long ull;
static __device__ __forceinline__ ull dup2(float x) {
    unsigned xi = __float_as_uint(x); ull r;
    asm("mov.b64 %0, {%1, %1};" : "=l"(r) : "r"(xi)); return r;
}
static __device__ __forceinline__ ull fma2(ull a, ull b, ull c) {
    ull d; asm("fma.rn.f32x2 %0, %1, %2, %3;" : "=l"(d) : "l"(a), "l"(b), "l"(c)); return d;
}
static __device__ __forceinline__ float2 unp2(ull v) {
    unsigned lo, hi; asm("mov.b64 {%0, %1}, %2;" : "=r"(lo), "=r"(hi) : "l"(v));
    return make_float2(__uint_as_float(lo), __uint_as_float(hi));
}

// ============ fwd (blocks 0..127) + gram/W3T (blocks 128..143) ============
__global__ void __launch_bounds__(256, 1)
fwdgram_kernel(const float* __restrict__ x,
               const float* __restrict__ W1, const float* __restrict__ b1,
               const float* __restrict__ W2, const float* __restrict__ b2,
               const float* __restrict__ W3, const float* __restrict__ b3)
{
    extern __shared__ float sm[];
    const int tid = threadIdx.x;
    const int tx = tid & 15, ty = tid >> 4;

    if (blockIdx.x >= 128) {
        float* At  = sm;
        float* Bt2 = sm + 64 * 65;
        const int t = blockIdx.x - 128;
        const int bi = t >> 2, bj = t & 3;

        for (int e = t * 256 + tid; e < 256 * 64; e += 16 * 256) {
            int i = e >> 6, o = e & 63;
            g_W3T[e] = W3[(size_t)o * 256 + i];
        }

        float acc[4][4];
        #pragma unroll
        for (int i = 0; i < 4; i++)
            #pragma unroll
            for (int u = 0; u < 4; u++) acc[i][u] = 0.f;

        for (int kc = 0; kc < 4; kc++) {
            __syncthreads();
            for (int e = tid; e < 64 * 16; e += 256) {
                int r = e >> 4, c4 = e & 15;
                float4 va = reinterpret_cast<const float4*>(W1)[(size_t)(bi * 64 + r) * 64 + kc * 16 + c4];
                At[r * 65 + c4 * 4 + 0] = va.x; At[r * 65 + c4 * 4 + 1] = va.y;
                At[r * 65 + c4 * 4 + 2] = va.z; At[r * 65 + c4 * 4 + 3] = va.w;
                float4 vb = reinterpret_cast<const float4*>(W1)[(size_t)(bj * 64 + r) * 64 + kc * 16 + c4];
                Bt2[r * 65 + c4 * 4 + 0] = vb.x; Bt2[r * 65 + c4 * 4 + 1] = vb.y;
                Bt2[r * 65 + c4 * 4 + 2] = vb.z; Bt2[r * 65 + c4 * 4 + 3] = vb.w;
            }
            __syncthreads();
            #pragma unroll 4
            for (int k = 0; k < 64; k++) {
                float a[4], b[4];
                #pragma unroll
                for (int i = 0; i < 4; i++) a[i] = At[(ty * 4 + i) * 65 + k];
                #pragma unroll
                for (int u = 0; u < 4; u++) b[u] = Bt2[(tx * 4 + u) * 65 + k];
                #pragma unroll
                for (int i = 0; i < 4; i++)
                    #pragma unroll
                    for (int u = 0; u < 4; u++)
                        acc[i][u] = fmaf(a[i], b[u], acc[i][u]);
            }
        }
        #pragma unroll
        for (int i = 0; i < 4; i++)
            #pragma unroll
            for (int u = 0; u < 4; u++)
                g_G[(size_t)(bi * 64 + ty * 4 + i) * 256 + bj * 64 + tx * 4 + u] = acc[i][u];
        return;
    }

    float* bufA = sm;
    float* bufB = bufA + 64 * FST;
    float* wt   = bufB + 64 * FST;
    const int s0 = blockIdx.x * 64;

    for (int e = tid; e < 64 * 64; e += 256) {
        int r = e >> 6, c = e & 63;
        float4 v = reinterpret_cast<const float4*>(x)[(size_t)(s0 + r) * 64 + c];
        float* d = &bufA[r * FST + c * 4];
        d[0] = v.x; d[1] = v.y; d[2] = v.z; d[3] = v.w;
    }
    __syncthreads();

    const float* Ws[3] = {W1, W2, W3};
    const float* bs[3] = {b1, b2, b3};
    float* ib = bufA;
    float* ob = bufB;

    for (int L = 0; L < 3; L++) {
        const int HO = (L == 2) ? 64 : 256;
        for (int oc = 0; oc < HO / 64; oc++) {
            __syncthreads();
            for (int e = tid; e < 64 * 64; e += 256) {
                int r = e >> 6, c = e & 63;
                float4 v = reinterpret_cast<const float4*>(Ws[L])[(size_t)(oc * 64 + r) * 64 + c];
                float* d = &wt[r * FST + c * 4];
                d[0] = v.x; d[1] = v.y; d[2] = v.z; d[3] = v.w;
            }
            __syncthreads();

            float acc[4][4];
            #pragma unroll
            for (int u = 0; u < 4; u++) {
                float bv = bs[L][oc * 64 + tx + 16 * u];
                #pragma unroll
                for (int i = 0; i < 4; i++) acc[i][u] = bv;
            }
            #pragma unroll 4
            for (int k = 0; k < 256; k++) {
                float a[4], bv[4];
                #pragma unroll
                for (int i = 0; i < 4; i++) a[i] = ib[(ty * 4 + i) * FST + k];
                #pragma unroll
                for (int u = 0; u < 4; u++) bv[u] = wt[(tx + 16 * u) * FST + k];
                #pragma unroll
                for (int i = 0; i < 4; i++)
                    #pragma unroll
                    for (int u = 0; u < 4; u++)
                        acc[i][u] = fmaf(a[i], bv[u], acc[i][u]);
            }
            if (L < 2) {
                #pragma unroll
                for (int i = 0; i < 4; i++)
                    #pragma unroll
                    for (int u = 0; u < 4; u++)
                        ob[(ty * 4 + i) * FST + oc * 64 + tx + 16 * u] = fmaxf(acc[i][u], 0.f);
            } else {
                #pragma unroll
                for (int i = 0; i < 4; i++)
                    #pragma unroll
                    for (int u = 0; u < 4; u++)
                        g_f[(size_t)(s0 + ty * 4 + i) * 64 + tx + 16 * u] = acc[i][u];
            }
        }
        if (L < 2) {
            __syncthreads();
            unsigned* mg = L ? g_m2 : g_m1;
            for (int e = tid; e < 64 * 8; e += 256) {
                int s = e >> 3, w = e & 7;
                unsigned bits = 0;
                for (int bb = 0; bb < 32; bb++)
                    if (ob[s * FST + w * 32 + bb] > 0.f) bits |= 1u << bb;
                mg[(size_t)(s0 + s) * 8 + w] = bits;
            }
            float* t = ib; ib = ob; ob = t;
            __syncthreads();
        }
    }
}

// ===================== jac kernel v4 =====================
// phase1: Bt[o,j] = sum_{i in S2} W3T[i,o] * W2[i, idx1[j]]
//   staging: coalesced W2 rows -> Ws2 (overlaid on Bt region), LDS regather -> Wg
// phase2: q = sum_j M[j,j] G'[j,j] + 2 sum_{j<j'} M G'  (M, G symmetric)
#define CH     16
#define BT_ST  200
#define WS2_ST 257
#define WG_ST  200
#define AS_ST  68
#define O_BT   0                      // Bt[64*200] ; Ws2[16*257] overlays (4112 <= 12800)
#define O_WG   12800                  // Wg[16*200]
#define O_AS   16000                  // As[16*68]
#define O_IDX1 17088
#define O_IDX2 17344
#define O_CNT  17600
#define O_PC   17602
#define O_RED  17618
#define SMEMF  17632
#define SMEMB  (SMEMF * 4)

__global__ void __launch_bounds__(256, 3)
jac_kernel(const float* __restrict__ W2, const float* __restrict__ kp,
           float* __restrict__ out)
{
    extern __shared__ float sm[];
    float* Bt  = sm + O_BT;
    float* Ws2 = sm + O_BT;     // overlay: live only during chunk loop
    float* Wg  = sm + O_WG;
    float* As  = sm + O_AS;
    int* idx1  = (int*)(sm + O_IDX1);
    int* idx2  = (int*)(sm + O_IDX2);
    int* cnts  = (int*)(sm + O_CNT);
    int* pcnt  = (int*)(sm + O_PC);
    float* red = sm + O_RED;

    const int b = blockIdx.x;
    const int tid = threadIdx.x;

    // ---- mask compaction ----
    idx1[tid] = 0; idx2[tid] = 0;
    if (tid < 16) {
        int which = tid >> 3, w = tid & 7;
        unsigned word = (which ? g_m2 : g_m1)[(size_t)b * 8 + w];
        pcnt[tid] = __popc(word);
    }
    __syncthreads();
    if (tid < 16) {
        int which = tid >> 3, w = tid & 7;
        unsigned word = (which ? g_m2 : g_m1)[(size_t)b * 8 + w];
        int base = 0;
        for (int t = which * 8; t < which * 8 + w; t++) base += pcnt[t];
        int* idx = which ? idx2 : idx1;
        while (word) {
            int bp = __ffs(word) - 1; word &= word - 1;
            idx[base++] = w * 32 + bp;
        }
        if (w == 7) cnts[which] = base;
    }
    __syncthreads();
    const int cnt1 = min(cnts[0], 192);
    const int cnt2 = cnts[1];
    int NP = (cnt1 + 15) & ~15;
    if (NP == 0) NP = 16;
    const bool wide = (NP > 128);       // phase1 column window 192 vs 128
    const int nch = (cnt2 + CH - 1) / CH;

    // ---- phase1 ----
    const int og = tid >> 4;   // 16 groups x 4 o
    const int jg = tid & 15;   // 16 groups x (8 or 12) j
    ull acc[4][6];
    #pragma unroll
    for (int k = 0; k < 4; k++)
        #pragma unroll
        for (int c = 0; c < 6; c++) acc[k][c] = 0ull;

    for (int ch = 0; ch < nch; ch++) {
        const int i0 = ch * CH;
        __syncthreads();
        // coalesced W2 row staging (row 0 for padded ii; zeroed later by As)
        for (int e = tid; e < CH * 64; e += 256) {
            int ii = e >> 6, c4 = e & 63;
            int row = idx2[i0 + ii];
            float4 v = reinterpret_cast<const float4*>(W2)[(size_t)row * 64 + c4];
            float* d = &Ws2[ii * WS2_ST + c4 * 4];
            d[0] = v.x; d[1] = v.y; d[2] = v.z; d[3] = v.w;
        }
        // W3T staging (float4, zero for padded ii)
        {
            int ii = tid >> 4, c4 = tid & 15;
            float4 v = make_float4(0.f, 0.f, 0.f, 0.f);
            if (i0 + ii < cnt2)
                v = reinterpret_cast<const float4*>(g_W3T)[(size_t)idx2[i0 + ii] * 16 + c4];
            float* d = &As[ii * AS_ST + c4 * 4];
            d[0] = v.x; d[1] = v.y; d[2] = v.z; d[3] = v.w;
        }
        __syncthreads();
        // regather columns: Wg[ii][j] = Ws2[ii][idx1[j]]   (literal 192)
        for (int e = tid; e < CH * 192; e += 256) {
            int ii = e / 192, j = e - ii * 192;
            Wg[ii * WG_ST + j] = (j < cnt1) ? Ws2[ii * WS2_ST + idx1[j]] : 0.f;
        }
        __syncthreads();
        if (!wide) {
            #pragma unroll 2
            for (int ii = 0; ii < CH; ii++) {
                const float* as = &As[ii * AS_ST + og * 4];
                const float* wg = &Wg[ii * WG_ST + jg * 8];
                float2 a01 = unp2(*(const ull*)as);
                float2 a23 = unp2(*(const ull*)(as + 2));
                ull w0 = *(const ull*)wg,       w1 = *(const ull*)(wg + 2);
                ull w2v = *(const ull*)(wg + 4), w3v = *(const ull*)(wg + 6);
                ull d0 = dup2(a01.x), d1 = dup2(a01.y), d2 = dup2(a23.x), d3 = dup2(a23.y);
                acc[0][0]=fma2(d0,w0,acc[0][0]); acc[0][1]=fma2(d0,w1,acc[0][1]);
                acc[0][2]=fma2(d0,w2v,acc[0][2]); acc[0][3]=fma2(d0,w3v,acc[0][3]);
                acc[1][0]=fma2(d1,w0,acc[1][0]); acc[1][1]=fma2(d1,w1,acc[1][1]);
                acc[1][2]=fma2(d1,w2v,acc[1][2]); acc[1][3]=fma2(d1,w3v,acc[1][3]);
                acc[2][0]=fma2(d2,w0,acc[2][0]); acc[2][1]=fma2(d2,w1,acc[2][1]);
                acc[2][2]=fma2(d2,w2v,acc[2][2]); acc[2][3]=fma2(d2,w3v,acc[2][3]);
                acc[3][0]=fma2(d3,w0,acc[3][0]); acc[3][1]=fma2(d3,w1,acc[3][1]);
                acc[3][2]=fma2(d3,w2v,acc[3][2]); acc[3][3]=fma2(d3,w3v,acc[3][3]);
            }
        } else {
            #pragma unroll 2
            for (int ii = 0; ii < CH; ii++) {
                const float* as = &As[ii * AS_ST + og * 4];
                const float* wg = &Wg[ii * WG_ST + jg * 12];
                float2 a01 = unp2(*(const ull*)as);
                float2 a23 = unp2(*(const ull*)(as + 2));
                ull wv[6];
                #pragma unroll
                for (int c = 0; c < 6; c++) wv[c] = *(const ull*)(wg + 2 * c);
                ull d0 = dup2(a01.x), d1 = dup2(a01.y), d2 = dup2(a23.x), d3 = dup2(a23.y);
                #pragma unroll
                for (int c = 0; c < 6; c++) {
                    acc[0][c] = fma2(d0, wv[c], acc[0][c]);
                    acc[1][c] = fma2(d1, wv[c], acc[1][c]);
                    acc[2][c] = fma2(d2, wv[c], acc[2][c]);
                    acc[3][c] = fma2(d3, wv[c], acc[3][c]);
                }
            }
        }
    }
    __syncthreads();    // Ws2 dead; Bt region now safe to write
    if (!wide) {
        #pragma unroll
        for (int k = 0; k < 4; k++)
            #pragma unroll
            for (int c = 0; c < 4; c++)
                *(ull*)&Bt[(og * 4 + k) * BT_ST + jg * 8 + 2 * c] = acc[k][c];
    } else {
        #pragma unroll
        for (int k = 0; k < 4; k++)
            #pragma unroll
            for (int c = 0; c < 6; c++)
                *(ull*)&Bt[(og * 4 + k) * BT_ST + jg * 12 + 2 * c] = acc[k][c];
    }
    __syncthreads();

    // ---- phase2: upper-triangle tiles, pair-balanced flat iterator ----
    const int nrg = NP >> 3;            // even, >= 2
    const int ncg = NP >> 2;
    const int P = nrg >> 1;
    const int C = 2 * (nrg + 1);        // tiles per row-pair (constant)
    const int NT = P * C;
    float qacc = 0.f;

    for (int g = tid; g < NT; g += 256) {
        int pair = g / C;
        int t = g - pair * C;
        int cnt_r = ncg - 2 * pair;
        int rg, cg;
        if (t < cnt_r) { rg = pair; cg = 2 * pair + t; }
        else { int r2 = nrg - 1 - pair; rg = r2; cg = 2 * r2 + (t - cnt_r); }
        const int r0 = rg * 8, c0 = cg * 4;

        ull m[8][2];
        #pragma unroll
        for (int k = 0; k < 8; k++) { m[k][0] = 0ull; m[k][1] = 0ull; }
        #pragma unroll 2
        for (int o = 0; o < 64; o++) {
            const float* br = &Bt[o * BT_ST];
            ull b0 = *(const ull*)(br + c0), b1 = *(const ull*)(br + c0 + 2);
            #pragma unroll
            for (int kh = 0; kh < 2; kh++) {
                float2 pa = unp2(*(const ull*)(br + r0 + kh * 4));
                float2 pb = unp2(*(const ull*)(br + r0 + kh * 4 + 2));
                ull da = dup2(pa.x), db = dup2(pa.y), dc = dup2(pb.x), dd = dup2(pb.y);
                m[kh*4+0][0]=fma2(da,b0,m[kh*4+0][0]); m[kh*4+0][1]=fma2(da,b1,m[kh*4+0][1]);
                m[kh*4+1][0]=fma2(db,b0,m[kh*4+1][0]); m[kh*4+1][1]=fma2(db,b1,m[kh*4+1][1]);
                m[kh*4+2][0]=fma2(dc,b0,m[kh*4+2][0]); m[kh*4+2][1]=fma2(dc,b1,m[kh*4+2][1]);
                m[kh*4+3][0]=fma2(dd,b0,m[kh*4+3][0]); m[kh*4+3][1]=fma2(dd,b1,m[kh*4+3][1]);
            }
        }
        const int gc0 = idx1[c0], gc1 = idx1[c0 + 1];
        const int gc2 = idx1[c0 + 2], gc3 = idx1[c0 + 3];
        #pragma unroll
        for (int k = 0; k < 8; k++) {
            const int jr = r0 + k;
            const float* Gr = &g_G[(size_t)idx1[jr] * 256];
            float2 m0 = unp2(m[k][0]), m1 = unp2(m[k][1]);
            float w0 = (c0     > jr) ? 2.f : ((c0     == jr) ? 1.f : 0.f);
            float w1 = (c0 + 1 > jr) ? 2.f : ((c0 + 1 == jr) ? 1.f : 0.f);
            float w2 = (c0 + 2 > jr) ? 2.f : ((c0 + 2 == jr) ? 1.f : 0.f);
            float w3 = (c0 + 3 > jr) ? 2.f : ((c0 + 3 == jr) ? 1.f : 0.f);
            qacc += w0 * m0.x * Gr[gc0] + w1 * m0.y * Gr[gc1]
                  + w2 * m1.x * Gr[gc2] + w3 * m1.y * Gr[gc3];
        }
    }

    // ---- reduce + epilogue ----
    #pragma unroll
    for (int s = 16; s; s >>= 1) qacc += __shfl_xor_sync(0xFFFFFFFFu, qacc, s);
    if ((tid & 31) == 0) red[tid >> 5] = qacc;
    __syncthreads();
    if (tid == 0) {
        float t = 0.f;
        for (int i = 0; i < 8; i++) t += red[i];
        red[0] = t;
    }
    __syncthreads();
    const float qq = red[0];
    if (tid < 64) {
        float fv = g_f[(size_t)b * 64 + tid];
        float kk = kp[0];
        float sp = (kk > 20.f) ? kk : log1pf(expf(kk));
        out[(size_t)b * 64 + tid] = tanhf(sp * fv / (sqrtf(qq) + 1e-4f));
    }
}

extern "C" void kernel_launch(void* const* d_in, const int* in_sizes, int n_in,
                              void* d_out, int out_size) {
    const float* x  = (const float*)d_in[0];
    const float* W1 = (const float*)d_in[1];
    const float* b1 = (const float*)d_in[2];
    const float* W2 = (const float*)d_in[3];
    const float* b2 = (const float*)d_in[4];
    const float* W3 = (const float*)d_in[5];
    const float* b3 = (const float*)d_in[6];
    const float* k  = (const float*)d_in[7];
    float* out = (float*)d_out;

    const size_t sm_fwd = 3 * 64 * FST * sizeof(float);
    cudaFuncSetAttribute(fwdgram_kernel, cudaFuncAttributeMaxDynamicSharedMemorySize, (int)sm_fwd);
    cudaFuncSetAttribute(jac_kernel, cudaFuncAttributeMaxDynamicSharedMemorySize, SMEMB);

    fwdgram_kernel<<<144, 256, sm_fwd>>>(x, W1, b1, W2, b2, W3, b3);
    jac_kernel<<<NB, 256, SMEMB>>>(W2, k, out);
}

// round 8
// speedup vs baseline: 2.1059x; 1.5986x over previous
#include <cuda_runtime.h>
#include <cuda_bf16.h>
#include <cstdint>
#include <math.h>

#define NB   8192
#define FST  257

typedef unsigned long long ull;

// ---------------- device scratch ----------------
__device__ unsigned g_m1[NB * 8];
__device__ unsigned g_m2[NB * 8];
__device__ float    g_f[NB * 64];
__device__ __nv_bfloat16 g_A1b[64 * 256];   // bf16(W3) [o][i]
__device__ __nv_bfloat16 g_B1T[256 * 256];  // [j][i] = W2[i][j]
__device__ __nv_bfloat16 g_B2T[256 * 256];  // [d][j] = W1[j][d]

// ---------------- helpers ----------------
static __device__ __forceinline__ uint32_t smem_u32(const void* p) {
    uint32_t a;
    asm("{ .reg .u64 t; cvta.to.shared.u64 t, %1; cvt.u32.u64 %0, t; }" : "=r"(a) : "l"(p));
    return a;
}
#define CP_ASYNC16(dst, src) asm volatile("cp.async.cg.shared.global [%0], [%1], 16;" :: "r"(dst), "l"(src) : "memory")
#define CP_COMMIT()          asm volatile("cp.async.commit_group;" ::: "memory")
#define CP_WAIT0()           asm volatile("cp.async.wait_group 0;" ::: "memory")

static __device__ __forceinline__ void mma_bf16(float* c, uint32_t a0, uint32_t a1,
                                                uint32_t a2, uint32_t a3,
                                                uint32_t b0, uint32_t b1) {
    asm volatile("mma.sync.aligned.m16n8k16.row.col.f32.bf16.bf16.f32 "
        "{%0,%1,%2,%3}, {%4,%5,%6,%7}, {%8,%9}, {%0,%1,%2,%3};"
        : "+f"(c[0]), "+f"(c[1]), "+f"(c[2]), "+f"(c[3])
        : "r"(a0), "r"(a1), "r"(a2), "r"(a3), "r"(b0), "r"(b1));
}

// ---------------- prep: bf16 operand images ----------------
__global__ void __launch_bounds__(256)
prep_kernel(const float* __restrict__ W1, const float* __restrict__ W2,
            const float* __restrict__ W3)
{
    const int t0 = blockIdx.x * 256 + threadIdx.x;
    for (int e = t0; e < 65536; e += 64 * 256) {
        int r = e >> 8, c = e & 255;
        g_B1T[e] = __float2bfloat16(W2[(size_t)c * 256 + r]);   // [j=r][i=c] = W2[i][j]
        g_B2T[e] = __float2bfloat16(W1[(size_t)c * 256 + r]);   // [d=r][j=c] = W1[j][d]
    }
    for (int e = t0; e < 16384; e += 64 * 256)
        g_A1b[e] = __float2bfloat16(W3[e]);
}

// ---------------- forward: 3-layer MLP + masks (proven) ----------------
__global__ void __launch_bounds__(256, 1)
fwd_kernel(const float* __restrict__ x,
           const float* __restrict__ W1, const float* __restrict__ b1,
           const float* __restrict__ W2, const float* __restrict__ b2,
           const float* __restrict__ W3, const float* __restrict__ b3)
{
    extern __shared__ float sm[];
    float* bufA = sm;
    float* bufB = bufA + 64 * FST;
    float* wt   = bufB + 64 * FST;
    const int tid = threadIdx.x;
    const int s0 = blockIdx.x * 64;
    const int tx = tid & 15, ty = tid >> 4;

    for (int e = tid; e < 64 * 64; e += 256) {
        int r = e >> 6, c = e & 63;
        float4 v = reinterpret_cast<const float4*>(x)[(size_t)(s0 + r) * 64 + c];
        float* d = &bufA[r * FST + c * 4];
        d[0] = v.x; d[1] = v.y; d[2] = v.z; d[3] = v.w;
    }
    __syncthreads();

    const float* Ws[3] = {W1, W2, W3};
    const float* bs[3] = {b1, b2, b3};
    float* ib = bufA;
    float* ob = bufB;

    for (int L = 0; L < 3; L++) {
        const int HO = (L == 2) ? 64 : 256;
        for (int oc = 0; oc < HO / 64; oc++) {
            __syncthreads();
            for (int e = tid; e < 64 * 64; e += 256) {
                int r = e >> 6, c = e & 63;
                float4 v = reinterpret_cast<const float4*>(Ws[L])[(size_t)(oc * 64 + r) * 64 + c];
                float* d = &wt[r * FST + c * 4];
                d[0] = v.x; d[1] = v.y; d[2] = v.z; d[3] = v.w;
            }
            __syncthreads();

            float acc[4][4];
            #pragma unroll
            for (int u = 0; u < 4; u++) {
                float bv = bs[L][oc * 64 + tx + 16 * u];
                #pragma unroll
                for (int i = 0; i < 4; i++) acc[i][u] = bv;
            }
            #pragma unroll 4
            for (int k = 0; k < 256; k++) {
                float a[4], bv[4];
                #pragma unroll
                for (int i = 0; i < 4; i++) a[i] = ib[(ty * 4 + i) * FST + k];
                #pragma unroll
                for (int u = 0; u < 4; u++) bv[u] = wt[(tx + 16 * u) * FST + k];
                #pragma unroll
                for (int i = 0; i < 4; i++)
                    #pragma unroll
                    for (int u = 0; u < 4; u++)
                        acc[i][u] = fmaf(a[i], bv[u], acc[i][u]);
            }
            if (L < 2) {
                #pragma unroll
                for (int i = 0; i < 4; i++)
                    #pragma unroll
                    for (int u = 0; u < 4; u++)
                        ob[(ty * 4 + i) * FST + oc * 64 + tx + 16 * u] = fmaxf(acc[i][u], 0.f);
            } else {
                #pragma unroll
                for (int i = 0; i < 4; i++)
                    #pragma unroll
                    for (int u = 0; u < 4; u++)
                        g_f[(size_t)(s0 + ty * 4 + i) * 64 + tx + 16 * u] = acc[i][u];
            }
        }
        if (L < 2) {
            __syncthreads();
            unsigned* mg = L ? g_m2 : g_m1;
            for (int e = tid; e < 64 * 8; e += 256) {
                int s = e >> 3, w = e & 7;
                unsigned bits = 0;
                for (int bb = 0; bb < 32; bb++)
                    if (ob[s * FST + w * 32 + bb] > 0.f) bits |= 1u << bb;
                mg[(size_t)(s0 + s) * 8 + w] = bits;
            }
            float* t = ib; ib = ob; ob = t;
            __syncthreads();
        }
    }
}

// ---------------- mma.sync bf16 Jacobian kernel ----------------
// CTA b: samples 2b, 2b+1 (M=128 rows = 2x64 outputs).
// GEMM1: Bt[128,256] = A1(masked W3) @ W2   (B stored [j][i])
// A2 = bf16(mask_m1(Bt)) -> As (overwrite)
// GEMM2: H[128,256] = A2 @ W1               (B stored [d][j])
// q_s = ||H rows of sample s||^2 ; epilogue tanh(softplus(k) f / (sqrt(q)+1e-4))
#define AS_ST 264
#define BS_ST 136
#define AS_OFF 0
#define BS_OFF 67584
#define MS_OFF 137216
#define JAC_SMEM 137600

__global__ void __launch_bounds__(256, 1)
jacmma_kernel(const float* __restrict__ kp, float* __restrict__ out)
{
    extern __shared__ char smc[];
    __nv_bfloat16* As = (__nv_bfloat16*)(smc + AS_OFF);
    __nv_bfloat16* Bs = (__nv_bfloat16*)(smc + BS_OFF);
    unsigned* m1w = (unsigned*)(smc + MS_OFF);
    unsigned* m2w = m1w + 16;
    float* red = (float*)(m2w + 16);
    float* qv  = red + 8;

    const int tid = threadIdx.x;
    const int w = tid >> 5, lane = tid & 31;
    const int g = lane >> 2, tg = lane & 3;
    const int b = blockIdx.x;
    const int mw = (w >> 2) * 64, nw = (w & 3) * 64;
    const int s = w >> 2;
    const uint32_t sB = smem_u32(Bs);

    if (tid < 16) {
        m1w[tid] = g_m1[(size_t)(2 * b + (tid >> 3)) * 8 + (tid & 7)];
        m2w[tid] = g_m2[(size_t)(2 * b + (tid >> 3)) * 8 + (tid & 7)];
    }
    __syncthreads();

    // ---- A1 = masked bf16(W3), rows m = s*64+o ----
    for (int u = tid; u < 16384; u += 256) {
        int m = u >> 7, i = (u & 127) * 2;
        int ss = m >> 6, o = m & 63;
        unsigned bits = (m2w[ss * 8 + (i >> 5)] >> (i & 31)) & 3u;
        unsigned v = *(const unsigned*)&g_A1b[o * 256 + i];
        if (!(bits & 1)) v &= 0xFFFF0000u;
        if (!(bits & 2)) v &= 0x0000FFFFu;
        *(unsigned*)&As[m * AS_ST + i] = v;
    }

    float c[4][8][4];
    #pragma unroll
    for (int mt = 0; mt < 4; mt++)
        #pragma unroll
        for (int nt = 0; nt < 8; nt++)
            #pragma unroll
            for (int e = 0; e < 4; e++) c[mt][nt][e] = 0.f;

    // ================== GEMM1 ==================
    #pragma unroll 1
    for (int kc = 0; kc < 2; kc++) {
        __syncthreads();
        {   // stage B chunk: Bs[n=tid][kk 0..127] <- g_B1T[tid][kc*128 + ...]
            const char* src = (const char*)(g_B1T + (size_t)tid * 256 + kc * 128);
            uint32_t dst = sB + (uint32_t)(tid * BS_ST) * 2;
            #pragma unroll
            for (int u2 = 0; u2 < 16; u2++)
                CP_ASYNC16(dst + u2 * 16, src + u2 * 16);
            CP_COMMIT();
        }
        CP_WAIT0();
        __syncthreads();
        #pragma unroll
        for (int ks = 0; ks < 8; ks++) {
            const int kk = ks * 16;
            uint32_t bf[8][2];
            #pragma unroll
            for (int nt = 0; nt < 8; nt++) {
                const __nv_bfloat16* bp = &Bs[(nw + nt * 8 + g) * BS_ST + kk + tg * 2];
                bf[nt][0] = *(const uint32_t*)bp;
                bf[nt][1] = *(const uint32_t*)(bp + 8);
            }
            #pragma unroll
            for (int mt = 0; mt < 4; mt++) {
                const __nv_bfloat16* ap = &As[(mw + mt * 16 + g) * AS_ST + kc * 128 + kk + tg * 2];
                uint32_t a0 = *(const uint32_t*)ap;
                uint32_t a1 = *(const uint32_t*)(ap + 8 * AS_ST);
                uint32_t a2 = *(const uint32_t*)(ap + 8);
                uint32_t a3 = *(const uint32_t*)(ap + 8 * AS_ST + 8);
                #pragma unroll
                for (int nt = 0; nt < 8; nt++)
                    mma_bf16(c[mt][nt], a0, a1, a2, a3, bf[nt][0], bf[nt][1]);
            }
        }
    }
    __syncthreads();

    // ---- A2 = bf16(mask_m1(Bt)) -> As ----
    #pragma unroll
    for (int mt = 0; mt < 4; mt++) {
        const int r0 = mw + mt * 16 + g;
        #pragma unroll
        for (int nt = 0; nt < 8; nt++) {
            const int j0 = nw + nt * 8 + tg * 2;
            const unsigned word = m1w[s * 8 + (j0 >> 5)];
            const bool k0 = (word >> (j0 & 31)) & 1u;
            const bool k1 = (word >> ((j0 & 31) + 1)) & 1u;
            float* cc = c[mt][nt];
            unsigned lo0 = (unsigned)__bfloat16_as_ushort(__float2bfloat16(k0 ? cc[0] : 0.f));
            unsigned hi0 = (unsigned)__bfloat16_as_ushort(__float2bfloat16(k1 ? cc[1] : 0.f));
            *(unsigned*)&As[r0 * AS_ST + j0] = lo0 | (hi0 << 16);
            unsigned lo1 = (unsigned)__bfloat16_as_ushort(__float2bfloat16(k0 ? cc[2] : 0.f));
            unsigned hi1 = (unsigned)__bfloat16_as_ushort(__float2bfloat16(k1 ? cc[3] : 0.f));
            *(unsigned*)&As[(r0 + 8) * AS_ST + j0] = lo1 | (hi1 << 16);
        }
    }
    #pragma unroll
    for (int mt = 0; mt < 4; mt++)
        #pragma unroll
        for (int nt = 0; nt < 8; nt++)
            #pragma unroll
            for (int e = 0; e < 4; e++) c[mt][nt][e] = 0.f;

    // ================== GEMM2 ==================
    #pragma unroll 1
    for (int kc = 0; kc < 2; kc++) {
        __syncthreads();
        {
            const char* src = (const char*)(g_B2T + (size_t)tid * 256 + kc * 128);
            uint32_t dst = sB + (uint32_t)(tid * BS_ST) * 2;
            #pragma unroll
            for (int u2 = 0; u2 < 16; u2++)
                CP_ASYNC16(dst + u2 * 16, src + u2 * 16);
            CP_COMMIT();
        }
        CP_WAIT0();
        __syncthreads();
        #pragma unroll
        for (int ks = 0; ks < 8; ks++) {
            const int kk = ks * 16;
            uint32_t bf[8][2];
            #pragma unroll
            for (int nt = 0; nt < 8; nt++) {
                const __nv_bfloat16* bp = &Bs[(nw + nt * 8 + g) * BS_ST + kk + tg * 2];
                bf[nt][0] = *(const uint32_t*)bp;
                bf[nt][1] = *(const uint32_t*)(bp + 8);
            }
            #pragma unroll
            for (int mt = 0; mt < 4; mt++) {
                const __nv_bfloat16* ap = &As[(mw + mt * 16 + g) * AS_ST + kc * 128 + kk + tg * 2];
                uint32_t a0 = *(const uint32_t*)ap;
                uint32_t a1 = *(const uint32_t*)(ap + 8 * AS_ST);
                uint32_t a2 = *(const uint32_t*)(ap + 8);
                uint32_t a3 = *(const uint32_t*)(ap + 8 * AS_ST + 8);
                #pragma unroll
                for (int nt = 0; nt < 8; nt++)
                    mma_bf16(c[mt][nt], a0, a1, a2, a3, bf[nt][0], bf[nt][1]);
            }
        }
    }

    // ---- q reduction (acc = H; warp rows all in one sample) ----
    float q = 0.f;
    #pragma unroll
    for (int mt = 0; mt < 4; mt++)
        #pragma unroll
        for (int nt = 0; nt < 8; nt++)
            #pragma unroll
            for (int e = 0; e < 4; e++)
                q = fmaf(c[mt][nt][e], c[mt][nt][e], q);
    #pragma unroll
    for (int sft = 16; sft; sft >>= 1) q += __shfl_xor_sync(0xFFFFFFFFu, q, sft);
    if (lane == 0) red[w] = q;
    __syncthreads();
    if (tid < 2)
        qv[tid] = red[tid * 4] + red[tid * 4 + 1] + red[tid * 4 + 2] + red[tid * 4 + 3];
    __syncthreads();
    if (tid < 128) {
        int ss = tid >> 6, o = tid & 63;
        float fv = g_f[(size_t)(2 * b + ss) * 64 + o];
        float kk = kp[0];
        float sp = (kk > 20.f) ? kk : log1pf(expf(kk));
        out[(size_t)(2 * b + ss) * 64 + o] = tanhf(sp * fv / (sqrtf(qv[ss]) + 1e-4f));
    }
}

extern "C" void kernel_launch(void* const* d_in, const int* in_sizes, int n_in,
                              void* d_out, int out_size) {
    const float* x  = (const float*)d_in[0];
    const float* W1 = (const float*)d_in[1];
    const float* b1 = (const float*)d_in[2];
    const float* W2 = (const float*)d_in[3];
    const float* b2 = (const float*)d_in[4];
    const float* W3 = (const float*)d_in[5];
    const float* b3 = (const float*)d_in[6];
    const float* k  = (const float*)d_in[7];
    float* out = (float*)d_out;

    const size_t sm_fwd = 3 * 64 * FST * sizeof(float);
    cudaFuncSetAttribute(fwd_kernel, cudaFuncAttributeMaxDynamicSharedMemorySize, (int)sm_fwd);
    cudaFuncSetAttribute(jacmma_kernel, cudaFuncAttributeMaxDynamicSharedMemorySize, JAC_SMEM);

    prep_kernel<<<64, 256>>>(W1, W2, W3);
    fwd_kernel<<<128, 256, sm_fwd>>>(x, W1, b1, W2, b2, W3, b3);
    jacmma_kernel<<<NB / 2, 256, JAC_SMEM>>>(k, out);
}